// round 2
// baseline (speedup 1.0000x reference)
#include <cuda_runtime.h>

// Problem constants
#define BATCH   64
#define TSTEPS  512
#define IN_DIM  1024
#define HID     1024
#define MTOT    (BATCH * TSTEPS)           // 32768 rows of the GEMM

// ALPHA = exp(-1/20) rounded to fp32
#define ALPHA_F 0.95122942450071400909f

// Scratch for the synaptic currents I[b,t,h] (128 MiB).
__device__ float g_I[(size_t)MTOT * HID];

// ---------------------------------------------------------------------------
// GEMM: g_I[m, n] = sum_k x[m, k] * W[n, k]  + b[n]
// Strictly in-order ascending-k accumulation, single fp32 accumulator, FMA.
// 128x128 tile, BK=16, 256 threads, 8x8 per-thread microtile.
// ---------------------------------------------------------------------------
#define BM 128
#define BN 128
#define BK 16

__global__ __launch_bounds__(256, 2)
void snn_gemm_kernel(const float* __restrict__ A,      // x  [MTOT, IN_DIM]
                     const float* __restrict__ Wt,     // W  [HID, IN_DIM]
                     const float* __restrict__ bias)   // b  [HID]
{
    __shared__ float As[BK][BM];   // transposed A tile: As[k][m]
    __shared__ float Bs[BK][BN];   // transposed W tile: Bs[k][n]

    const int tid  = threadIdx.x;          // 0..255
    const int tx   = tid & 15;             // col group
    const int ty   = tid >> 4;             // row group
    const int row0 = blockIdx.y * BM;      // M offset
    const int col0 = blockIdx.x * BN;      // N offset

    float acc[8][8];
#pragma unroll
    for (int i = 0; i < 8; i++)
#pragma unroll
        for (int j = 0; j < 8; j++) acc[i][j] = 0.0f;

    for (int k0 = 0; k0 < IN_DIM; k0 += BK) {
#pragma unroll
        for (int i = 0; i < 2; i++) {
            const int f = tid + i * 256;       // 0..511
            const int r = f >> 2;              // row within tile (0..127)
            const int c = (f & 3) * 4;         // k offset within tile

            float4 av = *reinterpret_cast<const float4*>(
                A + (size_t)(row0 + r) * IN_DIM + k0 + c);
            As[c + 0][r] = av.x;
            As[c + 1][r] = av.y;
            As[c + 2][r] = av.z;
            As[c + 3][r] = av.w;

            float4 wv = *reinterpret_cast<const float4*>(
                Wt + (size_t)(col0 + r) * IN_DIM + k0 + c);
            Bs[c + 0][r] = wv.x;
            Bs[c + 1][r] = wv.y;
            Bs[c + 2][r] = wv.z;
            Bs[c + 3][r] = wv.w;
        }
        __syncthreads();

#pragma unroll
        for (int kk = 0; kk < BK; kk++) {
            float a[8], b[8];
            *reinterpret_cast<float4*>(&a[0]) =
                *reinterpret_cast<const float4*>(&As[kk][ty * 8]);
            *reinterpret_cast<float4*>(&a[4]) =
                *reinterpret_cast<const float4*>(&As[kk][ty * 8 + 4]);
            *reinterpret_cast<float4*>(&b[0]) =
                *reinterpret_cast<const float4*>(&Bs[kk][tx * 8]);
            *reinterpret_cast<float4*>(&b[4]) =
                *reinterpret_cast<const float4*>(&Bs[kk][tx * 8 + 4]);
#pragma unroll
            for (int i = 0; i < 8; i++)
#pragma unroll
                for (int j = 0; j < 8; j++)
                    acc[i][j] = fmaf(a[i], b[j], acc[i][j]);
        }
        __syncthreads();
    }

    // Bias: single rounded add after the full K sum (matches "einsum + b").
#pragma unroll
    for (int i = 0; i < 8; i++) {
        const int r = row0 + ty * 8 + i;
#pragma unroll
        for (int j = 0; j < 8; j += 4) {
            const int c = col0 + tx * 8 + j;
            float4 o;
            o.x = __fadd_rn(acc[i][j + 0], bias[c + 0]);
            o.y = __fadd_rn(acc[i][j + 1], bias[c + 1]);
            o.z = __fadd_rn(acc[i][j + 2], bias[c + 2]);
            o.w = __fadd_rn(acc[i][j + 3], bias[c + 3]);
            *reinterpret_cast<float4*>(&g_I[(size_t)r * HID + c]) = o;
        }
    }
}

// ---------------------------------------------------------------------------
// LIF scan: one thread per (b, h) neuron, sequential over t.
// ROUND 2 CHANGE: mem = fma.rn(alpha, mem, I) — single fused rounding,
// matching XLA's fmad-contracted "ALPHA * mem + I_t".
// ---------------------------------------------------------------------------
__global__ __launch_bounds__(256)
void snn_scan_kernel(float* __restrict__ spikes,     // [B, T, H]
                     float* __restrict__ mem_final)  // [B, H]
{
    const int idx = blockIdx.x * blockDim.x + threadIdx.x;   // 0..65535
    const int b = idx >> 10;          // / HID
    const int h = idx & (HID - 1);

    const float* ip = g_I + (size_t)b * TSTEPS * HID + h;
    float* sp = spikes + (size_t)b * TSTEPS * HID + h;

    float mem = 0.0f;
#pragma unroll 4
    for (int t = 0; t < TSTEPS; t++) {
        const float cur = ip[(size_t)t * HID];
        mem = fmaf(ALPHA_F, mem, cur);          // fused: one rounding
        const bool fire = (mem >= 1.0f);
        sp[(size_t)t * HID] = fire ? 1.0f : 0.0f;
        if (fire) mem = 0.0f;
    }
    mem_final[idx] = mem;
}

// ---------------------------------------------------------------------------
// Launch
// ---------------------------------------------------------------------------
extern "C" void kernel_launch(void* const* d_in, const int* in_sizes, int n_in,
                              void* d_out, int out_size)
{
    const float* x = (const float*)d_in[0];   // [B, T, IN_DIM]
    const float* W = (const float*)d_in[1];   // [HID, IN_DIM]
    const float* b = (const float*)d_in[2];   // [HID]

    float* out        = (float*)d_out;
    float* spikes     = out;                                  // [B, T, H]
    float* mem_final  = out + (size_t)BATCH * TSTEPS * HID;   // [B, H]

    dim3 ggrid(HID / BN, MTOT / BM);    // (8, 256)
    snn_gemm_kernel<<<ggrid, 256>>>(x, W, b);

    snn_scan_kernel<<<(BATCH * HID) / 256, 256>>>(spikes, mem_final);
}